// round 7
// baseline (speedup 1.0000x reference)
#include <cuda_runtime.h>

#define N_NODES 100000
#define N_EDGES 1600000
#define D 64

#define SCAN_BLK 1024
#define SCAN_NBLK 98                 // 98*1024 = 100352 >= 100000
#define SCAN_PAD (SCAN_NBLK * SCAN_BLK)

#define GEMM_BLOCKS 782              // 782*128 = 100096 >= N_NODES
#define FUSED_GRID 2346              // bid%3==2 -> gemm (782), else bin (1564)

// Scratch (static __device__ arrays: allowed).
__device__ int   g_count[SCAN_PAD];
__device__ int   g_excl[SCAN_PAD];
__device__ int   g_bsum[SCAN_NBLK];
__device__ int   g_rowptr[N_NODES];
__device__ int   g_cursor[N_NODES];
__device__ int2  g_edges[N_EDGES];    // (src, w-as-int) binned by dst
__device__ float g_Z[N_NODES * D];    // Z = X @ W (pre-transformed features)

// ---------------------------------------------------------------------------
// 1) histogram of destination nodes — 4 edges/thread.
// ---------------------------------------------------------------------------
__global__ __launch_bounds__(256) void hist_kernel(const int* __restrict__ dst) {
    int e0 = (blockIdx.x * blockDim.x + threadIdx.x) * 4;
    if (e0 + 3 < N_EDGES) {
        int4 t = *reinterpret_cast<const int4*>(&dst[e0]);
        atomicAdd(&g_count[t.x], 1);
        atomicAdd(&g_count[t.y], 1);
        atomicAdd(&g_count[t.z], 1);
        atomicAdd(&g_count[t.w], 1);
    } else {
        for (int e = e0; e < N_EDGES; e++) atomicAdd(&g_count[__ldg(&dst[e])], 1);
    }
}

// ---------------------------------------------------------------------------
// 2a) per-block exclusive scan via warp shuffles (2 barriers, not 20).
// ---------------------------------------------------------------------------
__global__ __launch_bounds__(SCAN_BLK) void scan_a_kernel() {
    __shared__ int warp_sums[32];
    int t = threadIdx.x;
    int gid = blockIdx.x * SCAN_BLK + t;
    int lane = t & 31, wid = t >> 5;
    int c = g_count[gid];

    // inclusive scan within warp
    int v = c;
    #pragma unroll
    for (int off = 1; off < 32; off <<= 1) {
        int n = __shfl_up_sync(0xFFFFFFFF, v, off);
        if (lane >= off) v += n;
    }
    if (lane == 31) warp_sums[wid] = v;
    __syncthreads();

    if (wid == 0) {
        int ws = warp_sums[lane];
        int s = ws;
        #pragma unroll
        for (int off = 1; off < 32; off <<= 1) {
            int n = __shfl_up_sync(0xFFFFFFFF, s, off);
            if (lane >= off) s += n;
        }
        warp_sums[lane] = s - ws;             // exclusive warp prefix
    }
    __syncthreads();

    g_excl[gid] = v - c + warp_sums[wid];     // block-exclusive
    if (t == SCAN_BLK - 1) g_bsum[blockIdx.x] = warp_sums[31] + v;
}

// 2b) finalize row_ptr (256 nodes per block lie inside one scan_a block).
__global__ __launch_bounds__(256) void scan_c_kernel() {
    __shared__ int s[SCAN_NBLK];
    __shared__ int prefix;
    int t = threadIdx.x;
    int sblk = blockIdx.x >> 2;
    if (t < SCAN_NBLK) s[t] = g_bsum[t];
    __syncthreads();
    if (t == 0) {
        int run = 0;
        for (int i = 0; i < sblk; i++) run += s[i];
        prefix = run;
    }
    __syncthreads();
    int i = blockIdx.x * 256 + t;
    if (i < N_NODES) {
        int v = g_excl[i] + prefix;
        g_rowptr[i] = v;
        g_cursor[i] = v;
    }
}

// ---------------------------------------------------------------------------
// 3) FUSED bin + gemm.  bid%3==2 -> 128x64 GEMM tile (8x4 regs/thread,
//    1.5B LDS per FMA). Other blocks: bin 4 edges/thread.
// ---------------------------------------------------------------------------
__global__ __launch_bounds__(256) void bin_gemm_kernel(
        const int*   __restrict__ src,
        const int*   __restrict__ dst,
        const float* __restrict__ w,
        const float* __restrict__ X,
        const float* __restrict__ W) {
    __shared__ float sm[D * D + 128 * D];    // Ws (16KB) + As (32KB) = 48KB

    int bid = blockIdx.x;
    int m3 = bid % 3;

    if (m3 == 2) {
        // ---------------- GEMM tile path: 128 rows x 64 cols ----------------
        int gemm_id = bid / 3;
        float* Ws = sm;                      // [k][c]  64x64
        float* As = sm + D * D;              // [r][k]  128x64
        int tid = threadIdx.x;
        int row0 = gemm_id * 128;

        const float4* W4 = reinterpret_cast<const float4*>(W);
        float4* Ws4 = reinterpret_cast<float4*>(Ws);
        #pragma unroll
        for (int i = tid; i < 1024; i += 256) Ws4[i] = W4[i];

        const float4* A4 = reinterpret_cast<const float4*>(X) + row0 * 16;
        float4* As4 = reinterpret_cast<float4*>(As);
        #pragma unroll
        for (int i = tid; i < 2048; i += 256) {
            int r = i >> 4;
            As4[i] = (row0 + r < N_NODES) ? A4[i]
                                          : make_float4(0.f, 0.f, 0.f, 0.f);
        }
        __syncthreads();

        int tx = tid & 15;
        int ty = tid >> 4;
        int c0 = tx * 4;
        int r0 = ty * 8;

        float4 acc[8];
        #pragma unroll
        for (int i = 0; i < 8; i++) acc[i] = make_float4(0.f, 0.f, 0.f, 0.f);

        #pragma unroll
        for (int k0 = 0; k0 < D; k0 += 4) {
            float4 wr0 = *reinterpret_cast<const float4*>(&Ws[(k0 + 0) * D + c0]);
            float4 wr1 = *reinterpret_cast<const float4*>(&Ws[(k0 + 1) * D + c0]);
            float4 wr2 = *reinterpret_cast<const float4*>(&Ws[(k0 + 2) * D + c0]);
            float4 wr3 = *reinterpret_cast<const float4*>(&Ws[(k0 + 3) * D + c0]);
            #pragma unroll
            for (int i = 0; i < 8; i++) {
                float4 av = *reinterpret_cast<const float4*>(&As[(r0 + i) * D + k0]);
                acc[i].x = fmaf(av.x, wr0.x, acc[i].x);
                acc[i].y = fmaf(av.x, wr0.y, acc[i].y);
                acc[i].z = fmaf(av.x, wr0.z, acc[i].z);
                acc[i].w = fmaf(av.x, wr0.w, acc[i].w);

                acc[i].x = fmaf(av.y, wr1.x, acc[i].x);
                acc[i].y = fmaf(av.y, wr1.y, acc[i].y);
                acc[i].z = fmaf(av.y, wr1.z, acc[i].z);
                acc[i].w = fmaf(av.y, wr1.w, acc[i].w);

                acc[i].x = fmaf(av.z, wr2.x, acc[i].x);
                acc[i].y = fmaf(av.z, wr2.y, acc[i].y);
                acc[i].z = fmaf(av.z, wr2.z, acc[i].z);
                acc[i].w = fmaf(av.z, wr2.w, acc[i].w);

                acc[i].x = fmaf(av.w, wr3.x, acc[i].x);
                acc[i].y = fmaf(av.w, wr3.y, acc[i].y);
                acc[i].z = fmaf(av.w, wr3.z, acc[i].z);
                acc[i].w = fmaf(av.w, wr3.w, acc[i].w);
            }
        }

        #pragma unroll
        for (int i = 0; i < 8; i++) {
            int row = row0 + r0 + i;
            if (row < N_NODES) {
                reinterpret_cast<float4*>(g_Z)[row * 16 + tx] = acc[i];
            }
        }
    } else {
        // ---------------- bin path: 4 edges/thread ----------------
        int bin_id = (bid / 3) * 2 + m3;     // 0..1564 (tail ids no-op)
        int e0 = (bin_id * 256 + threadIdx.x) * 4;
        if (e0 + 3 < N_EDGES) {
            int4   s = *reinterpret_cast<const int4*>(&src[e0]);
            int4   t = *reinterpret_cast<const int4*>(&dst[e0]);
            float4 v = *reinterpret_cast<const float4*>(&w[e0]);
            int p0 = atomicAdd(&g_cursor[t.x], 1);
            int p1 = atomicAdd(&g_cursor[t.y], 1);
            int p2 = atomicAdd(&g_cursor[t.z], 1);
            int p3 = atomicAdd(&g_cursor[t.w], 1);
            g_edges[p0] = make_int2(s.x, __float_as_int(v.x));
            g_edges[p1] = make_int2(s.y, __float_as_int(v.y));
            g_edges[p2] = make_int2(s.z, __float_as_int(v.z));
            g_edges[p3] = make_int2(s.w, __float_as_int(v.w));
        } else {
            for (int e = e0; e < N_EDGES; e++) {
                int t = __ldg(&dst[e]);
                int pos = atomicAdd(&g_cursor[t], 1);
                g_edges[pos] = make_int2(__ldg(&src[e]),
                                         __float_as_int(__ldg(&w[e])));
            }
        }
    }
}

// ---------------------------------------------------------------------------
// 4) gather-reduce over Z + bias + relu -> out.  One warp per node; halves
//    interleave edges; each half unrolls by 2 (4 gathers in flight / warp).
// ---------------------------------------------------------------------------
__global__ __launch_bounds__(256) void gather_out_kernel(
        const float* __restrict__ b,
        float* __restrict__ out) {
    int gtid = blockIdx.x * blockDim.x + threadIdx.x;
    int node = gtid >> 5;
    int lane = gtid & 31;
    if (node >= N_NODES) return;
    int half = lane >> 4;
    int l    = lane & 15;

    int beg = __ldg(&g_rowptr[node]);
    int end = (node == N_NODES - 1) ? N_EDGES : __ldg(&g_rowptr[node + 1]);

    const float4* z4 = reinterpret_cast<const float4*>(g_Z);
    float4 a0 = make_float4(0.f, 0.f, 0.f, 0.f);
    float4 a1 = make_float4(0.f, 0.f, 0.f, 0.f);

    int j = beg + half;
    for (; j + 2 < end; j += 4) {              // two independent chains
        int2 p0 = g_edges[j];
        int2 p1 = g_edges[j + 2];
        float4 f0 = __ldg(&z4[p0.x * 16 + l]);
        float4 f1 = __ldg(&z4[p1.x * 16 + l]);
        float w0 = __int_as_float(p0.y);
        float w1 = __int_as_float(p1.y);
        a0.x = fmaf(w0, f0.x, a0.x);
        a0.y = fmaf(w0, f0.y, a0.y);
        a0.z = fmaf(w0, f0.z, a0.z);
        a0.w = fmaf(w0, f0.w, a0.w);
        a1.x = fmaf(w1, f1.x, a1.x);
        a1.y = fmaf(w1, f1.y, a1.y);
        a1.z = fmaf(w1, f1.z, a1.z);
        a1.w = fmaf(w1, f1.w, a1.w);
    }
    for (; j < end; j += 2) {
        int2 p = g_edges[j];
        float4 f = __ldg(&z4[p.x * 16 + l]);
        float wv = __int_as_float(p.y);
        a0.x = fmaf(wv, f.x, a0.x);
        a0.y = fmaf(wv, f.y, a0.y);
        a0.z = fmaf(wv, f.z, a0.z);
        a0.w = fmaf(wv, f.w, a0.w);
    }

    float4 acc;
    acc.x = a0.x + a1.x;
    acc.y = a0.y + a1.y;
    acc.z = a0.z + a1.z;
    acc.w = a0.w + a1.w;

    acc.x += __shfl_xor_sync(0xFFFFFFFF, acc.x, 16);
    acc.y += __shfl_xor_sync(0xFFFFFFFF, acc.y, 16);
    acc.z += __shfl_xor_sync(0xFFFFFFFF, acc.z, 16);
    acc.w += __shfl_xor_sync(0xFFFFFFFF, acc.w, 16);

    if (half == 0) {
        float4 bv = __ldg(&reinterpret_cast<const float4*>(b)[l]);
        float4 r;
        r.x = fmaxf(acc.x + bv.x, 0.f);
        r.y = fmaxf(acc.y + bv.y, 0.f);
        r.z = fmaxf(acc.z + bv.z, 0.f);
        r.w = fmaxf(acc.w + bv.w, 0.f);
        reinterpret_cast<float4*>(out)[node * 16 + l] = r;
    }
}

// ---------------------------------------------------------------------------
// Launch
// ---------------------------------------------------------------------------
extern "C" void kernel_launch(void* const* d_in, const int* in_sizes, int n_in,
                              void* d_out, int out_size) {
    const float* features = (const float*)d_in[0];   // [N_NODES, D]
    const int*   edge_src = (const int*)  d_in[1];   // [N_EDGES]
    const int*   edge_dst = (const int*)  d_in[2];   // [N_EDGES]
    const float* edge_w   = (const float*)d_in[3];   // [N_EDGES]
    const float* W        = (const float*)d_in[4];   // [D, D]
    const float* b        = (const float*)d_in[5];   // [1, D]
    float* out = (float*)d_out;                      // [N_NODES, D]

    void* count_ptr = nullptr;
    cudaGetSymbolAddress(&count_ptr, g_count);
    cudaMemsetAsync(count_ptr, 0, SCAN_PAD * sizeof(int));

    {
        int threads_total = (N_EDGES + 3) / 4;
        hist_kernel<<<(threads_total + 255) / 256, 256>>>(edge_dst);
    }
    scan_a_kernel<<<SCAN_NBLK, SCAN_BLK>>>();
    scan_c_kernel<<<(N_NODES + 255) / 256, 256>>>();

    bin_gemm_kernel<<<FUSED_GRID, 256>>>(edge_src, edge_dst, edge_w,
                                         features, W);

    {
        long long threads_total = (long long)N_NODES * 32;
        int blocks = (int)((threads_total + 255) / 256);
        gather_out_kernel<<<blocks, 256>>>(b, out);
    }
}

// round 8
// speedup vs baseline: 1.0724x; 1.0724x over previous
#include <cuda_runtime.h>

#define N_NODES 100000
#define N_EDGES 1600000
#define D 64

#define SCAN_BLK 1024
#define SCAN_NBLK 98                 // 98*1024 = 100352 >= 100000
#define SCAN_PAD (SCAN_NBLK * SCAN_BLK)

#define BIN_BLOCKS  1563             // 1563*256*4 = 1600512 >= N_EDGES
#define GEMM_BLOCKS 1563             // 1563*64 = 100032 >= N_NODES

// Scratch (static __device__ arrays: allowed).
__device__ int   g_count[SCAN_PAD];
__device__ int   g_excl[SCAN_PAD];
__device__ int   g_bsum[SCAN_NBLK];
__device__ int   g_rowptr[N_NODES];
__device__ int   g_cursor[N_NODES];
__device__ int2  g_edges[N_EDGES];    // (src, w-as-int) binned by dst
__device__ float g_Z[N_NODES * D];    // Z = X @ W (pre-transformed features)

// ---------------------------------------------------------------------------
// 1) histogram of destination nodes — 4 edges/thread.
// ---------------------------------------------------------------------------
__global__ __launch_bounds__(256) void hist_kernel(const int* __restrict__ dst) {
    int e0 = (blockIdx.x * blockDim.x + threadIdx.x) * 4;
    if (e0 + 3 < N_EDGES) {
        int4 t = *reinterpret_cast<const int4*>(&dst[e0]);
        atomicAdd(&g_count[t.x], 1);
        atomicAdd(&g_count[t.y], 1);
        atomicAdd(&g_count[t.z], 1);
        atomicAdd(&g_count[t.w], 1);
    } else {
        for (int e = e0; e < N_EDGES; e++) atomicAdd(&g_count[__ldg(&dst[e])], 1);
    }
}

// ---------------------------------------------------------------------------
// 2a) per-block exclusive scan via warp shuffles (2 barriers).
// ---------------------------------------------------------------------------
__global__ __launch_bounds__(SCAN_BLK) void scan_a_kernel() {
    __shared__ int warp_sums[32];
    int t = threadIdx.x;
    int gid = blockIdx.x * SCAN_BLK + t;
    int lane = t & 31, wid = t >> 5;
    int c = g_count[gid];

    int v = c;                                 // inclusive scan within warp
    #pragma unroll
    for (int off = 1; off < 32; off <<= 1) {
        int n = __shfl_up_sync(0xFFFFFFFF, v, off);
        if (lane >= off) v += n;
    }
    if (lane == 31) warp_sums[wid] = v;
    __syncthreads();

    if (wid == 0) {
        int ws = warp_sums[lane];
        int s = ws;
        #pragma unroll
        for (int off = 1; off < 32; off <<= 1) {
            int n = __shfl_up_sync(0xFFFFFFFF, s, off);
            if (lane >= off) s += n;
        }
        warp_sums[lane] = s - ws;              // exclusive warp prefix
    }
    __syncthreads();

    g_excl[gid] = v - c + warp_sums[wid];      // block-exclusive
    if (t == SCAN_BLK - 1) g_bsum[blockIdx.x] = warp_sums[31] + v;
}

// 2b) finalize row_ptr (256 nodes per block lie inside one scan_a block).
__global__ __launch_bounds__(256) void scan_c_kernel() {
    __shared__ int s[SCAN_NBLK];
    __shared__ int prefix;
    int t = threadIdx.x;
    int sblk = blockIdx.x >> 2;
    if (t < SCAN_NBLK) s[t] = g_bsum[t];
    __syncthreads();
    if (t == 0) {
        int run = 0;
        for (int i = 0; i < sblk; i++) run += s[i];
        prefix = run;
    }
    __syncthreads();
    int i = blockIdx.x * 256 + t;
    if (i < N_NODES) {
        int v = g_excl[i] + prefix;
        g_rowptr[i] = v;
        g_cursor[i] = v;
    }
}

// ---------------------------------------------------------------------------
// 3) FUSED bin + gemm (R6 config: 64x64 tile, 32KB smem, occ ~44%).
// ---------------------------------------------------------------------------
__global__ __launch_bounds__(256) void bin_gemm_kernel(
        const int*   __restrict__ src,
        const int*   __restrict__ dst,
        const float* __restrict__ w,
        const float* __restrict__ X,
        const float* __restrict__ W) {
    __shared__ float sm[2 * D * D];          // gemm path only (32 KB)

    int part_id = blockIdx.x >> 1;

    if (blockIdx.x & 1) {
        // ---------------- GEMM tile path ----------------
        float* Ws = sm;                      // [k][c]
        float* As = sm + D * D;              // [r][k]
        int tid = threadIdx.x;
        int row0 = part_id * 64;

        const float4* W4 = reinterpret_cast<const float4*>(W);
        float4* Ws4 = reinterpret_cast<float4*>(Ws);
        #pragma unroll
        for (int i = tid; i < 1024; i += 256) Ws4[i] = W4[i];

        const float4* A4 = reinterpret_cast<const float4*>(X) + row0 * 16;
        float4* As4 = reinterpret_cast<float4*>(As);
        #pragma unroll
        for (int i = tid; i < 1024; i += 256) {
            int r = i >> 4;
            As4[i] = (row0 + r < N_NODES) ? A4[i]
                                          : make_float4(0.f, 0.f, 0.f, 0.f);
        }
        __syncthreads();

        int tx = tid & 15;
        int ty = tid >> 4;
        int c0 = tx * 4;
        int r0 = ty * 4;

        float4 acc[4];
        #pragma unroll
        for (int i = 0; i < 4; i++) acc[i] = make_float4(0.f, 0.f, 0.f, 0.f);

        #pragma unroll
        for (int k0 = 0; k0 < D; k0 += 4) {
            float4 wr0 = *reinterpret_cast<const float4*>(&Ws[(k0 + 0) * D + c0]);
            float4 wr1 = *reinterpret_cast<const float4*>(&Ws[(k0 + 1) * D + c0]);
            float4 wr2 = *reinterpret_cast<const float4*>(&Ws[(k0 + 2) * D + c0]);
            float4 wr3 = *reinterpret_cast<const float4*>(&Ws[(k0 + 3) * D + c0]);
            #pragma unroll
            for (int i = 0; i < 4; i++) {
                float4 av = *reinterpret_cast<const float4*>(&As[(r0 + i) * D + k0]);
                acc[i].x = fmaf(av.x, wr0.x, acc[i].x);
                acc[i].y = fmaf(av.x, wr0.y, acc[i].y);
                acc[i].z = fmaf(av.x, wr0.z, acc[i].z);
                acc[i].w = fmaf(av.x, wr0.w, acc[i].w);

                acc[i].x = fmaf(av.y, wr1.x, acc[i].x);
                acc[i].y = fmaf(av.y, wr1.y, acc[i].y);
                acc[i].z = fmaf(av.y, wr1.z, acc[i].z);
                acc[i].w = fmaf(av.y, wr1.w, acc[i].w);

                acc[i].x = fmaf(av.z, wr2.x, acc[i].x);
                acc[i].y = fmaf(av.z, wr2.y, acc[i].y);
                acc[i].z = fmaf(av.z, wr2.z, acc[i].z);
                acc[i].w = fmaf(av.z, wr2.w, acc[i].w);

                acc[i].x = fmaf(av.w, wr3.x, acc[i].x);
                acc[i].y = fmaf(av.w, wr3.y, acc[i].y);
                acc[i].z = fmaf(av.w, wr3.z, acc[i].z);
                acc[i].w = fmaf(av.w, wr3.w, acc[i].w);
            }
        }

        #pragma unroll
        for (int i = 0; i < 4; i++) {
            int row = row0 + r0 + i;
            if (row < N_NODES) {
                reinterpret_cast<float4*>(g_Z)[row * 16 + tx] = acc[i];
            }
        }
    } else {
        // ---------------- bin path: 4 edges/thread ----------------
        int e0 = (part_id * 256 + threadIdx.x) * 4;
        if (e0 + 3 < N_EDGES) {
            int4   s = *reinterpret_cast<const int4*>(&src[e0]);
            int4   t = *reinterpret_cast<const int4*>(&dst[e0]);
            float4 v = *reinterpret_cast<const float4*>(&w[e0]);
            int p0 = atomicAdd(&g_cursor[t.x], 1);
            int p1 = atomicAdd(&g_cursor[t.y], 1);
            int p2 = atomicAdd(&g_cursor[t.z], 1);
            int p3 = atomicAdd(&g_cursor[t.w], 1);
            g_edges[p0] = make_int2(s.x, __float_as_int(v.x));
            g_edges[p1] = make_int2(s.y, __float_as_int(v.y));
            g_edges[p2] = make_int2(s.z, __float_as_int(v.z));
            g_edges[p3] = make_int2(s.w, __float_as_int(v.w));
        } else {
            for (int e = e0; e < N_EDGES; e++) {
                int t = __ldg(&dst[e]);
                int pos = atomicAdd(&g_cursor[t], 1);
                g_edges[pos] = make_int2(__ldg(&src[e]),
                                         __float_as_int(__ldg(&w[e])));
            }
        }
    }
}

// ---------------------------------------------------------------------------
// 4) gather-reduce over Z + bias + relu -> out.  One warp per node.
//    Warp loads a 32-edge batch with ONE coalesced load, then broadcasts
//    (src,w) via shfl; half-warps process even/odd batch entries, each
//    lane gathering one float4 of the 256B row. All gathers in a batch
//    are independent -> deep MLP.
// ---------------------------------------------------------------------------
__global__ __launch_bounds__(256) void gather_out_kernel(
        const float* __restrict__ b,
        float* __restrict__ out) {
    int gtid = blockIdx.x * blockDim.x + threadIdx.x;
    int node = gtid >> 5;
    int lane = gtid & 31;
    if (node >= N_NODES) return;
    int half = lane >> 4;
    int l    = lane & 15;

    int beg = __ldg(&g_rowptr[node]);
    int end = (node == N_NODES - 1) ? N_EDGES : __ldg(&g_rowptr[node + 1]);

    const float4* z4 = reinterpret_cast<const float4*>(g_Z);
    float4 acc = make_float4(0.f, 0.f, 0.f, 0.f);

    for (int base = beg; base < end; base += 32) {
        int idx = base + lane;
        int2 e = (idx < end) ? g_edges[idx] : make_int2(0, 0);
        int n = end - base;                    // edges in this batch (<=32 used)
        if (n > 32) n = 32;

        #pragma unroll 4
        for (int k2 = 0; k2 < n; k2 += 2) {
            int k = k2 + half;                 // half0: even, half1: odd
            int kk = (k < n) ? k : (n - 1);    // keep shfl convergent
            int   sx = __shfl_sync(0xFFFFFFFF, e.x, kk);
            float wv = __int_as_float(__shfl_sync(0xFFFFFFFF, e.y, kk));
            if (k >= n) wv = 0.f;
            float4 f = __ldg(&z4[sx * 16 + l]);
            acc.x = fmaf(wv, f.x, acc.x);
            acc.y = fmaf(wv, f.y, acc.y);
            acc.z = fmaf(wv, f.z, acc.z);
            acc.w = fmaf(wv, f.w, acc.w);
        }
    }

    acc.x += __shfl_xor_sync(0xFFFFFFFF, acc.x, 16);
    acc.y += __shfl_xor_sync(0xFFFFFFFF, acc.y, 16);
    acc.z += __shfl_xor_sync(0xFFFFFFFF, acc.z, 16);
    acc.w += __shfl_xor_sync(0xFFFFFFFF, acc.w, 16);

    if (half == 0) {
        float4 bv = __ldg(&reinterpret_cast<const float4*>(b)[l]);
        float4 r;
        r.x = fmaxf(acc.x + bv.x, 0.f);
        r.y = fmaxf(acc.y + bv.y, 0.f);
        r.z = fmaxf(acc.z + bv.z, 0.f);
        r.w = fmaxf(acc.w + bv.w, 0.f);
        reinterpret_cast<float4*>(out)[node * 16 + l] = r;
    }
}

// ---------------------------------------------------------------------------
// Launch
// ---------------------------------------------------------------------------
extern "C" void kernel_launch(void* const* d_in, const int* in_sizes, int n_in,
                              void* d_out, int out_size) {
    const float* features = (const float*)d_in[0];   // [N_NODES, D]
    const int*   edge_src = (const int*)  d_in[1];   // [N_EDGES]
    const int*   edge_dst = (const int*)  d_in[2];   // [N_EDGES]
    const float* edge_w   = (const float*)d_in[3];   // [N_EDGES]
    const float* W        = (const float*)d_in[4];   // [D, D]
    const float* b        = (const float*)d_in[5];   // [1, D]
    float* out = (float*)d_out;                      // [N_NODES, D]

    void* count_ptr = nullptr;
    cudaGetSymbolAddress(&count_ptr, g_count);
    cudaMemsetAsync(count_ptr, 0, SCAN_PAD * sizeof(int));

    {
        int threads_total = (N_EDGES + 3) / 4;
        hist_kernel<<<(threads_total + 255) / 256, 256>>>(edge_dst);
    }
    scan_a_kernel<<<SCAN_NBLK, SCAN_BLK>>>();
    scan_c_kernel<<<(N_NODES + 255) / 256, 256>>>();

    bin_gemm_kernel<<<BIN_BLOCKS + GEMM_BLOCKS, 256>>>(
        edge_src, edge_dst, edge_w, features, W);

    {
        long long threads_total = (long long)N_NODES * 32;
        int blocks = (int)((threads_total + 255) / 256);
        gather_out_kernel<<<blocks, 256>>>(b, out);
    }
}

// round 9
// speedup vs baseline: 1.1280x; 1.0519x over previous
#include <cuda_runtime.h>
#include <cuda_fp16.h>

#define N_NODES 100000
#define N_EDGES 1600000
#define D 64

#define SCAN_BLK 1024
#define SCAN_NBLK 98                 // 98*1024 = 100352 >= 100000
#define SCAN_PAD (SCAN_NBLK * SCAN_BLK)

#define BIN_BLOCKS  1563             // 1563*256*4 = 1600512 >= N_EDGES
#define GEMM_BLOCKS 1563             // 1563*64 = 100032 >= N_NODES

// Scratch (static __device__ arrays: allowed).
__device__ int   g_count[SCAN_PAD];
__device__ int   g_excl[SCAN_PAD];
__device__ int   g_bsum[SCAN_NBLK];
__device__ int   g_rowptr[N_NODES];
__device__ int   g_cursor[N_NODES];
__device__ int2  g_edges[N_EDGES];    // (src, w-as-int) binned by dst
__device__ uint2 g_Zh[N_NODES * 16];  // Z = X @ W in fp16: 64 halves/row = 128B

// ---------------------------------------------------------------------------
// 1) histogram of destination nodes — 4 edges/thread.
// ---------------------------------------------------------------------------
__global__ __launch_bounds__(256) void hist_kernel(const int* __restrict__ dst) {
    int e0 = (blockIdx.x * blockDim.x + threadIdx.x) * 4;
    if (e0 + 3 < N_EDGES) {
        int4 t = *reinterpret_cast<const int4*>(&dst[e0]);
        atomicAdd(&g_count[t.x], 1);
        atomicAdd(&g_count[t.y], 1);
        atomicAdd(&g_count[t.z], 1);
        atomicAdd(&g_count[t.w], 1);
    } else {
        for (int e = e0; e < N_EDGES; e++) atomicAdd(&g_count[__ldg(&dst[e])], 1);
    }
}

// ---------------------------------------------------------------------------
// 2a) per-block exclusive scan via warp shuffles (2 barriers).
// ---------------------------------------------------------------------------
__global__ __launch_bounds__(SCAN_BLK) void scan_a_kernel() {
    __shared__ int warp_sums[32];
    int t = threadIdx.x;
    int gid = blockIdx.x * SCAN_BLK + t;
    int lane = t & 31, wid = t >> 5;
    int c = g_count[gid];

    int v = c;                                 // inclusive scan within warp
    #pragma unroll
    for (int off = 1; off < 32; off <<= 1) {
        int n = __shfl_up_sync(0xFFFFFFFF, v, off);
        if (lane >= off) v += n;
    }
    if (lane == 31) warp_sums[wid] = v;
    __syncthreads();

    if (wid == 0) {
        int ws = warp_sums[lane];
        int s = ws;
        #pragma unroll
        for (int off = 1; off < 32; off <<= 1) {
            int n = __shfl_up_sync(0xFFFFFFFF, s, off);
            if (lane >= off) s += n;
        }
        warp_sums[lane] = s - ws;              // exclusive warp prefix
    }
    __syncthreads();

    g_excl[gid] = v - c + warp_sums[wid];      // block-exclusive
    if (t == SCAN_BLK - 1) g_bsum[blockIdx.x] = warp_sums[31] + v;
}

// 2b) finalize row_ptr (256 nodes per block lie inside one scan_a block).
__global__ __launch_bounds__(256) void scan_c_kernel() {
    __shared__ int s[SCAN_NBLK];
    __shared__ int prefix;
    int t = threadIdx.x;
    int sblk = blockIdx.x >> 2;
    if (t < SCAN_NBLK) s[t] = g_bsum[t];
    __syncthreads();
    if (t == 0) {
        int run = 0;
        for (int i = 0; i < sblk; i++) run += s[i];
        prefix = run;
    }
    __syncthreads();
    int i = blockIdx.x * 256 + t;
    if (i < N_NODES) {
        int v = g_excl[i] + prefix;
        g_rowptr[i] = v;
        g_cursor[i] = v;
    }
}

// ---------------------------------------------------------------------------
// 3) FUSED bin + gemm (64x64 tile, 32KB smem, occ ~44%).
//    GEMM computes in fp32, stores Z rounded to fp16 (half the epilogue bytes).
// ---------------------------------------------------------------------------
__global__ __launch_bounds__(256) void bin_gemm_kernel(
        const int*   __restrict__ src,
        const int*   __restrict__ dst,
        const float* __restrict__ w,
        const float* __restrict__ X,
        const float* __restrict__ W) {
    __shared__ float sm[2 * D * D];          // gemm path only (32 KB)

    int part_id = blockIdx.x >> 1;

    if (blockIdx.x & 1) {
        // ---------------- GEMM tile path ----------------
        float* Ws = sm;                      // [k][c]
        float* As = sm + D * D;              // [r][k]
        int tid = threadIdx.x;
        int row0 = part_id * 64;

        const float4* W4 = reinterpret_cast<const float4*>(W);
        float4* Ws4 = reinterpret_cast<float4*>(Ws);
        #pragma unroll
        for (int i = tid; i < 1024; i += 256) Ws4[i] = W4[i];

        const float4* A4 = reinterpret_cast<const float4*>(X) + row0 * 16;
        float4* As4 = reinterpret_cast<float4*>(As);
        #pragma unroll
        for (int i = tid; i < 1024; i += 256) {
            int r = i >> 4;
            As4[i] = (row0 + r < N_NODES) ? A4[i]
                                          : make_float4(0.f, 0.f, 0.f, 0.f);
        }
        __syncthreads();

        int tx = tid & 15;
        int ty = tid >> 4;
        int c0 = tx * 4;
        int r0 = ty * 4;

        float4 acc[4];
        #pragma unroll
        for (int i = 0; i < 4; i++) acc[i] = make_float4(0.f, 0.f, 0.f, 0.f);

        #pragma unroll
        for (int k0 = 0; k0 < D; k0 += 4) {
            float4 wr0 = *reinterpret_cast<const float4*>(&Ws[(k0 + 0) * D + c0]);
            float4 wr1 = *reinterpret_cast<const float4*>(&Ws[(k0 + 1) * D + c0]);
            float4 wr2 = *reinterpret_cast<const float4*>(&Ws[(k0 + 2) * D + c0]);
            float4 wr3 = *reinterpret_cast<const float4*>(&Ws[(k0 + 3) * D + c0]);
            #pragma unroll
            for (int i = 0; i < 4; i++) {
                float4 av = *reinterpret_cast<const float4*>(&As[(r0 + i) * D + k0]);
                acc[i].x = fmaf(av.x, wr0.x, acc[i].x);
                acc[i].y = fmaf(av.x, wr0.y, acc[i].y);
                acc[i].z = fmaf(av.x, wr0.z, acc[i].z);
                acc[i].w = fmaf(av.x, wr0.w, acc[i].w);

                acc[i].x = fmaf(av.y, wr1.x, acc[i].x);
                acc[i].y = fmaf(av.y, wr1.y, acc[i].y);
                acc[i].z = fmaf(av.y, wr1.z, acc[i].z);
                acc[i].w = fmaf(av.y, wr1.w, acc[i].w);

                acc[i].x = fmaf(av.z, wr2.x, acc[i].x);
                acc[i].y = fmaf(av.z, wr2.y, acc[i].y);
                acc[i].z = fmaf(av.z, wr2.z, acc[i].z);
                acc[i].w = fmaf(av.z, wr2.w, acc[i].w);

                acc[i].x = fmaf(av.w, wr3.x, acc[i].x);
                acc[i].y = fmaf(av.w, wr3.y, acc[i].y);
                acc[i].z = fmaf(av.w, wr3.z, acc[i].z);
                acc[i].w = fmaf(av.w, wr3.w, acc[i].w);
            }
        }

        #pragma unroll
        for (int i = 0; i < 4; i++) {
            int row = row0 + r0 + i;
            if (row < N_NODES) {
                __half2 h01 = __floats2half2_rn(acc[i].x, acc[i].y);
                __half2 h23 = __floats2half2_rn(acc[i].z, acc[i].w);
                uint2 packed;
                packed.x = *reinterpret_cast<unsigned int*>(&h01);
                packed.y = *reinterpret_cast<unsigned int*>(&h23);
                g_Zh[row * 16 + tx] = packed;
            }
        }
    } else {
        // ---------------- bin path: 4 edges/thread ----------------
        int e0 = (part_id * 256 + threadIdx.x) * 4;
        if (e0 + 3 < N_EDGES) {
            int4   s = *reinterpret_cast<const int4*>(&src[e0]);
            int4   t = *reinterpret_cast<const int4*>(&dst[e0]);
            float4 v = *reinterpret_cast<const float4*>(&w[e0]);
            int p0 = atomicAdd(&g_cursor[t.x], 1);
            int p1 = atomicAdd(&g_cursor[t.y], 1);
            int p2 = atomicAdd(&g_cursor[t.z], 1);
            int p3 = atomicAdd(&g_cursor[t.w], 1);
            g_edges[p0] = make_int2(s.x, __float_as_int(v.x));
            g_edges[p1] = make_int2(s.y, __float_as_int(v.y));
            g_edges[p2] = make_int2(s.z, __float_as_int(v.z));
            g_edges[p3] = make_int2(s.w, __float_as_int(v.w));
        } else {
            for (int e = e0; e < N_EDGES; e++) {
                int t = __ldg(&dst[e]);
                int pos = atomicAdd(&g_cursor[t], 1);
                g_edges[pos] = make_int2(__ldg(&src[e]),
                                         __float_as_int(__ldg(&w[e])));
            }
        }
    }
}

// ---------------------------------------------------------------------------
// 4) gather-reduce over fp16 Z + bias + relu -> fp32 out.  One warp per
//    node; 32-edge coalesced batches + shfl broadcast; half-warps process
//    even/odd edges, each lane loads 8B (4 halves = 4 columns). fp32 accum.
// ---------------------------------------------------------------------------
__global__ __launch_bounds__(256) void gather_out_kernel(
        const float* __restrict__ b,
        float* __restrict__ out) {
    int gtid = blockIdx.x * blockDim.x + threadIdx.x;
    int node = gtid >> 5;
    int lane = gtid & 31;
    if (node >= N_NODES) return;
    int half = lane >> 4;
    int l    = lane & 15;

    int beg = __ldg(&g_rowptr[node]);
    int end = (node == N_NODES - 1) ? N_EDGES : __ldg(&g_rowptr[node + 1]);

    float4 acc = make_float4(0.f, 0.f, 0.f, 0.f);

    for (int base = beg; base < end; base += 32) {
        int idx = base + lane;
        int2 e = (idx < end) ? g_edges[idx] : make_int2(0, 0);
        int n = end - base;
        if (n > 32) n = 32;

        #pragma unroll 4
        for (int k2 = 0; k2 < n; k2 += 2) {
            int k = k2 + half;                 // half0: even, half1: odd
            int kk = (k < n) ? k : (n - 1);    // keep shfl convergent
            int   sx = __shfl_sync(0xFFFFFFFF, e.x, kk);
            float wv = __int_as_float(__shfl_sync(0xFFFFFFFF, e.y, kk));
            if (k >= n) wv = 0.f;

            uint2 zv = __ldg(&g_Zh[sx * 16 + l]);
            __half2 h01 = *reinterpret_cast<__half2*>(&zv.x);
            __half2 h23 = *reinterpret_cast<__half2*>(&zv.y);
            float2 f01 = __half22float2(h01);
            float2 f23 = __half22float2(h23);
            acc.x = fmaf(wv, f01.x, acc.x);
            acc.y = fmaf(wv, f01.y, acc.y);
            acc.z = fmaf(wv, f23.x, acc.z);
            acc.w = fmaf(wv, f23.y, acc.w);
        }
    }

    acc.x += __shfl_xor_sync(0xFFFFFFFF, acc.x, 16);
    acc.y += __shfl_xor_sync(0xFFFFFFFF, acc.y, 16);
    acc.z += __shfl_xor_sync(0xFFFFFFFF, acc.z, 16);
    acc.w += __shfl_xor_sync(0xFFFFFFFF, acc.w, 16);

    if (half == 0) {
        float4 bv = __ldg(&reinterpret_cast<const float4*>(b)[l]);
        float4 r;
        r.x = fmaxf(acc.x + bv.x, 0.f);
        r.y = fmaxf(acc.y + bv.y, 0.f);
        r.z = fmaxf(acc.z + bv.z, 0.f);
        r.w = fmaxf(acc.w + bv.w, 0.f);
        reinterpret_cast<float4*>(out)[node * 16 + l] = r;
    }
}

// ---------------------------------------------------------------------------
// Launch
// ---------------------------------------------------------------------------
extern "C" void kernel_launch(void* const* d_in, const int* in_sizes, int n_in,
                              void* d_out, int out_size) {
    const float* features = (const float*)d_in[0];   // [N_NODES, D]
    const int*   edge_src = (const int*)  d_in[1];   // [N_EDGES]
    const int*   edge_dst = (const int*)  d_in[2];   // [N_EDGES]
    const float* edge_w   = (const float*)d_in[3];   // [N_EDGES]
    const float* W        = (const float*)d_in[4];   // [D, D]
    const float* b        = (const float*)d_in[5];   // [1, D]
    float* out = (float*)d_out;                      // [N_NODES, D]

    void* count_ptr = nullptr;
    cudaGetSymbolAddress(&count_ptr, g_count);
    cudaMemsetAsync(count_ptr, 0, SCAN_PAD * sizeof(int));

    {
        int threads_total = (N_EDGES + 3) / 4;
        hist_kernel<<<(threads_total + 255) / 256, 256>>>(edge_dst);
    }
    scan_a_kernel<<<SCAN_NBLK, SCAN_BLK>>>();
    scan_c_kernel<<<(N_NODES + 255) / 256, 256>>>();

    bin_gemm_kernel<<<BIN_BLOCKS + GEMM_BLOCKS, 256>>>(
        edge_src, edge_dst, edge_w, features, W);

    {
        long long threads_total = (long long)N_NODES * 32;
        int blocks = (int)((threads_total + 255) / 256);
        gather_out_kernel<<<blocks, 256>>>(b, out);
    }
}